// round 9
// baseline (speedup 1.0000x reference)
#include <cuda_runtime.h>
#include <cuda_bf16.h>

// SegEncodeLoss round 9 (= r8 re-run after container flake): LDG.32 streaming.
// All prior rounds (LDG.128 and TMA alike) capped at ~15-17 B/cyc/SM =
// the within-LDG L1tex wavefront replay rate (2.07 cyc/wf x 16 sectors for
// LDG.128). Cross-LDG rate is 1.0 cyc/wf and the LDG->LDG floor is 4 cyc,
// so a stream of coalesced LDG.32 (1 line/warp-op) sustains ~32 B/cyc/SM.
// One warp per tile: 32 LDG.32 rows, double-buffered 8-row batches.

constexpr int Cc   = 19;
constexpr int NBLK = 32768;             // 32x32-tiles
constexpr int WPC  = 8;                 // warps (tiles) per CTA
constexpr int NCTA = NBLK / WPC;        // 4096

__device__ float    g_part[NCTA];
__device__ unsigned g_count = 0;        // wraps to 0 via atomicInc limit

__device__ __forceinline__ float bce_logit(float x, float t) {
    return fmaxf(x, 0.0f) - x * t + log1pf(__expf(-fabsf(x)));
}

__global__ void __launch_bounds__(256) seg_ldg32_kernel(
    const float* __restrict__ preds,
    const int*   __restrict__ targets,
    float*       __restrict__ out)
{
    const int tid  = threadIdx.x;
    const int warp = tid >> 5;
    const int lane = tid & 31;

    const int n  = blockIdx.x * WPC + warp;   // tile id
    const int b  = n >> 10;
    const int bh = (n >> 5) & 31;
    const int bw = n & 31;

    // Prefetch logit (independent of targets traffic).
    float x = 0.0f;
    if (lane < Cc) x = __ldg(&preds[n * Cc + lane]);

    // Warp reads one 128B row per LDG.32: lane = column within tile row.
    const int* base = targets
                    + ((size_t)b << 20)
                    + ((size_t)(bh * 32) << 10)
                    + (size_t)(bw * 32 + lane);

    unsigned m = 0u;
    int v[8], w[8];

    #pragma unroll
    for (int r = 0; r < 8; r++) v[r] = __ldg(base + r * 1024);

    #pragma unroll
    for (int batch = 1; batch < 4; batch++) {
        #pragma unroll
        for (int r = 0; r < 8; r++)
            w[r] = __ldg(base + (batch * 8 + r) * 1024);
        #pragma unroll
        for (int r = 0; r < 8; r++)
            m |= 1u << v[r];
        #pragma unroll
        for (int r = 0; r < 8; r++)
            v[r] = w[r];
    }
    #pragma unroll
    for (int r = 0; r < 8; r++)
        m |= 1u << v[r];

    m = __reduce_or_sync(0xffffffffu, m);     // full 32x32 tile mask

    float loss = 0.0f;
    if (lane < Cc)
        loss = bce_logit(x, (float)((m >> lane) & 1u));
    #pragma unroll
    for (int o = 16; o > 0; o >>= 1)
        loss += __shfl_down_sync(0xffffffffu, loss, o);

    __shared__ float s_part[WPC];
    if (lane == 0) s_part[warp] = loss;
    __syncthreads();
    if (warp != 0) return;                    // only warp0 pays the atomic

    float cs = (lane < WPC) ? s_part[lane] : 0.0f;
    #pragma unroll
    for (int o = 4; o > 0; o >>= 1)
        cs += __shfl_down_sync(0xffffffffu, cs, o);

    int is_last = 0;
    if (lane == 0) {
        g_part[blockIdx.x] = cs;
        __threadfence();
        unsigned old = atomicInc(&g_count, NCTA - 1u);   // replay-safe wrap
        is_last = (old == NCTA - 1u);
    }
    is_last = __shfl_sync(0xffffffffu, is_last, 0);
    if (!is_last) return;

    // Last CTA's warp0: reduce 4096 partials (hot in L2).
    double sd = 0.0;
    for (int i = lane; i < NCTA; i += 32)
        sd += (double)__ldcg(&g_part[i]);
    #pragma unroll
    for (int o = 16; o > 0; o >>= 1)
        sd += __shfl_down_sync(0xffffffffu, sd, o);
    if (lane == 0)
        out[0] = (float)(sd / ((double)NBLK * (double)Cc));
}

extern "C" void kernel_launch(void* const* d_in, const int* in_sizes, int n_in,
                              void* d_out, int out_size) {
    const float* preds   = (const float*)d_in[0];
    const int*   targets = (const int*)d_in[1];
    float*       out     = (float*)d_out;

    seg_ldg32_kernel<<<NCTA, 256>>>(preds, targets, out);
}

// round 10
// speedup vs baseline: 1.3053x; 1.3053x over previous
#include <cuda_runtime.h>
#include <cuda_bf16.h>
#include <cstdint>

// SegEncodeLoss round 10: HYBRID ingest (TMA + LDG.128 concurrently).
// Evidence r2-r9: per-SM ingest ceilings are path-specific — LDG.128 ~15.5
// B/cyc, bulk-async ~19-20 B/cyc (per-op fixed cost ~180cyc; 32KB chunks
// amortize it), LDG.32 issue-bound. Neither path alone reaches DRAM roofline.
// So: each CTA takes one 128KB band; rows 0-15 stream via two 32KB
// cp.async.bulk chunks (consumed by warps 0-3 from smem), rows 16-31 are
// read by warps 4-7 with LDG.128 directly. Both per-SM engines run at once.

constexpr int Cc      = 19;
constexpr int NBLK    = 32768;           // tiles
constexpr int NCTA    = 1024;            // 1 band (32 tiles = 128KB) per CTA
constexpr int CHUNK_B = 32768;           // 8 rows

__device__ float    g_part[NCTA];
__device__ unsigned g_count = 0;         // wraps to 0 via atomicInc limit

__device__ __forceinline__ uint32_t smem_u32(const void* p) {
    uint32_t a;
    asm("{ .reg .u64 t; cvta.to.shared.u64 t, %1; cvt.u32.u64 %0, t; }"
        : "=r"(a) : "l"(p));
    return a;
}
__device__ __forceinline__ void mbar_init(uint32_t mbar, uint32_t cnt) {
    asm volatile("mbarrier.init.shared.b64 [%0], %1;" :: "r"(mbar), "r"(cnt) : "memory");
}
__device__ __forceinline__ void mbar_expect_tx(uint32_t mbar, uint32_t bytes) {
    asm volatile("mbarrier.arrive.expect_tx.shared.b64 _, [%0], %1;"
                 :: "r"(mbar), "r"(bytes) : "memory");
}
__device__ __forceinline__ void bulk_g2s(uint32_t dst, const void* src,
                                         uint32_t bytes, uint32_t mbar) {
    asm volatile(
        "cp.async.bulk.shared::cta.global.mbarrier::complete_tx::bytes "
        "[%0], [%1], %2, [%3];"
        :: "r"(dst), "l"(src), "r"(bytes), "r"(mbar) : "memory");
}
__device__ __forceinline__ void mbar_wait(uint32_t mbar, uint32_t parity) {
    asm volatile(
        "{\n\t"
        ".reg .pred P;\n\t"
        "WL_%=:\n\t"
        "mbarrier.try_wait.parity.acquire.cta.shared::cta.b64 P, [%0], %1, 0x989680;\n\t"
        "@P bra.uni WD_%=;\n\t"
        "bra.uni WL_%=;\n\t"
        "WD_%=:\n\t"
        "}"
        :: "r"(mbar), "r"(parity) : "memory");
}
__device__ __forceinline__ float bce_logit(float x, float t) {
    return fmaxf(x, 0.0f) - x * t + log1pf(__expf(-fabsf(x)));
}
__device__ __forceinline__ void or4(unsigned& m, const int4& v) {
    m |= (1u << v.x) | (1u << v.y) | (1u << v.z) | (1u << v.w);
}

__global__ void __launch_bounds__(256, 3) seg_hybrid_kernel(
    const float* __restrict__ preds,
    const int*   __restrict__ targets,
    float*       __restrict__ out)
{
    extern __shared__ char smem[];
    int4*     buf      = reinterpret_cast<int4*>(smem);                 // 2 x 32KB
    uint64_t* mbar_mem = reinterpret_cast<uint64_t*>(smem + 2 * CHUNK_B);
    unsigned* s_maskA  = reinterpret_cast<unsigned*>(smem + 2 * CHUNK_B + 64);   // [32]
    unsigned* s_maskB  = s_maskA + 32;                                           // [32]
    float*    s_part   = reinterpret_cast<float*>(s_maskB + 32);                 // [8]

    const int tid  = threadIdx.x;
    const int warp = tid >> 5;
    const int lane = tid & 31;
    const uint32_t mb0 = smem_u32(&mbar_mem[0]);
    const uint32_t mb1 = smem_u32(&mbar_mem[1]);

    if (tid == 0) { mbar_init(mb0, 1); mbar_init(mb1, 1); }
    __syncthreads();

    const int band = blockIdx.x;
    const int4* gsrc = reinterpret_cast<const int4*>(targets)
                     + (size_t)band * 8192;          // 128KB = 8192 int4

    // Issue both 32KB TMA chunks for rows 0-15 (each mbarrier used once).
    if (tid == 0) {
        mbar_expect_tx(mb0, CHUNK_B);
        bulk_g2s(smem_u32(&buf[0]),    gsrc,        CHUNK_B, mb0);
        mbar_expect_tx(mb1, CHUNK_B);
        bulk_g2s(smem_u32(&buf[2048]), gsrc + 2048, CHUNK_B, mb1);
    }

    // Prefetch this warp's 4 BCE logit rows (overlaps all ingest).
    const int n0 = band * 32 + warp * 4;
    float xr0 = 0, xr1 = 0, xr2 = 0, xr3 = 0;
    if (lane < Cc) {
        xr0 = __ldg(&preds[(n0 + 0) * Cc + lane]);
        xr1 = __ldg(&preds[(n0 + 1) * Cc + lane]);
        xr2 = __ldg(&preds[(n0 + 2) * Cc + lane]);
        xr3 = __ldg(&preds[(n0 + 3) * Cc + lane]);
    }

    // Stripe layout (both halves): a row is 256 int4 spanning 32 tiles
    // (8 int4/tile). Warp-group index w owns int4 cols [64w, 64w+64) =
    // tiles 8w..8w+7. Lane reads idx (64w+lane) and (64w+lane+32):
    // bank-conflict-free, contributing to tiles 8w+(lane>>3) and 8w+4+(lane>>3).

    if (warp < 4) {
        // ---- TMA half: rows 0-15 from smem ----
        unsigned mA = 0u, mB = 0u;
        #pragma unroll
        for (int c = 0; c < 2; c++) {
            mbar_wait(c ? mb1 : mb0, 0);
            const int4* bb = buf + c * 2048 + warp * 64 + lane;
            #pragma unroll
            for (int r = 0; r < 8; r++) {
                int4 a = bb[r * 256];
                int4 b = bb[r * 256 + 32];
                or4(mA, a); or4(mB, b);
            }
        }
        mA |= __shfl_xor_sync(0xffffffffu, mA, 1);
        mA |= __shfl_xor_sync(0xffffffffu, mA, 2);
        mA |= __shfl_xor_sync(0xffffffffu, mA, 4);
        mB |= __shfl_xor_sync(0xffffffffu, mB, 1);
        mB |= __shfl_xor_sync(0xffffffffu, mB, 2);
        mB |= __shfl_xor_sync(0xffffffffu, mB, 4);
        if ((lane & 7) == 0) {
            s_maskA[warp * 8 + (lane >> 3)]     = mA;
            s_maskA[warp * 8 + 4 + (lane >> 3)] = mB;
        }
    } else {
        // ---- LDG half: rows 16-31 straight from global ----
        const int w2 = warp - 4;
        const int4* gb = gsrc + 4096 + w2 * 64 + lane;   // row 16 base
        unsigned mA = 0u, mB = 0u;
        #pragma unroll
        for (int batch = 0; batch < 4; batch++) {
            int4 a0 = __ldg(gb + (batch * 4 + 0) * 256);
            int4 b0 = __ldg(gb + (batch * 4 + 0) * 256 + 32);
            int4 a1 = __ldg(gb + (batch * 4 + 1) * 256);
            int4 b1 = __ldg(gb + (batch * 4 + 1) * 256 + 32);
            int4 a2 = __ldg(gb + (batch * 4 + 2) * 256);
            int4 b2 = __ldg(gb + (batch * 4 + 2) * 256 + 32);
            int4 a3 = __ldg(gb + (batch * 4 + 3) * 256);
            int4 b3 = __ldg(gb + (batch * 4 + 3) * 256 + 32);
            or4(mA, a0); or4(mB, b0);
            or4(mA, a1); or4(mB, b1);
            or4(mA, a2); or4(mB, b2);
            or4(mA, a3); or4(mB, b3);
        }
        mA |= __shfl_xor_sync(0xffffffffu, mA, 1);
        mA |= __shfl_xor_sync(0xffffffffu, mA, 2);
        mA |= __shfl_xor_sync(0xffffffffu, mA, 4);
        mB |= __shfl_xor_sync(0xffffffffu, mB, 1);
        mB |= __shfl_xor_sync(0xffffffffu, mB, 2);
        mB |= __shfl_xor_sync(0xffffffffu, mB, 4);
        if ((lane & 7) == 0) {
            s_maskB[w2 * 8 + (lane >> 3)]     = mA;
            s_maskB[w2 * 8 + 4 + (lane >> 3)] = mB;
        }
    }
    __syncthreads();

    // BCE: warp w handles tiles w*4 .. w*4+3; mask = TMA half | LDG half.
    float acc = 0.0f;
    if (lane < Cc) {
        const unsigned m0 = s_maskA[warp * 4 + 0] | s_maskB[warp * 4 + 0];
        const unsigned m1 = s_maskA[warp * 4 + 1] | s_maskB[warp * 4 + 1];
        const unsigned m2 = s_maskA[warp * 4 + 2] | s_maskB[warp * 4 + 2];
        const unsigned m3 = s_maskA[warp * 4 + 3] | s_maskB[warp * 4 + 3];
        acc += bce_logit(xr0, (float)((m0 >> lane) & 1u));
        acc += bce_logit(xr1, (float)((m1 >> lane) & 1u));
        acc += bce_logit(xr2, (float)((m2 >> lane) & 1u));
        acc += bce_logit(xr3, (float)((m3 >> lane) & 1u));
    }
    #pragma unroll
    for (int o = 16; o > 0; o >>= 1)
        acc += __shfl_down_sync(0xffffffffu, acc, o);
    if (lane == 0) s_part[warp] = acc;
    __syncthreads();
    if (warp != 0) return;

    float cs = (lane < 8) ? s_part[lane] : 0.0f;
    #pragma unroll
    for (int o = 4; o > 0; o >>= 1)
        cs += __shfl_down_sync(0xffffffffu, cs, o);

    int is_last = 0;
    if (lane == 0) {
        g_part[blockIdx.x] = cs;
        __threadfence();
        unsigned old = atomicInc(&g_count, NCTA - 1u);   // replay-safe wrap
        is_last = (old == NCTA - 1u);
    }
    is_last = __shfl_sync(0xffffffffu, is_last, 0);
    if (!is_last) return;

    double sd = 0.0;
    for (int i = lane; i < NCTA; i += 32)
        sd += (double)__ldcg(&g_part[i]);
    #pragma unroll
    for (int o = 16; o > 0; o >>= 1)
        sd += __shfl_down_sync(0xffffffffu, sd, o);
    if (lane == 0)
        out[0] = (float)(sd / ((double)NBLK * (double)Cc));
}

extern "C" void kernel_launch(void* const* d_in, const int* in_sizes, int n_in,
                              void* d_out, int out_size) {
    const float* preds   = (const float*)d_in[0];
    const int*   targets = (const int*)d_in[1];
    float*       out     = (float*)d_out;

    const int smem_bytes = 2 * CHUNK_B + 64 + 256 + 64;
    cudaFuncSetAttribute(seg_hybrid_kernel,
                         cudaFuncAttributeMaxDynamicSharedMemorySize, smem_bytes);
    seg_hybrid_kernel<<<NCTA, 256, smem_bytes>>>(preds, targets, out);
}